// round 15
// baseline (speedup 1.0000x reference)
#include <cuda_runtime.h>
#include <math.h>

#define NBOX   4096
#define RPB    128                      // pred rows per pair block
#define CHUNK  128                      // targets per pair block
#define NBLK   1024                     // 32x32 pair blocks
#define CBLK   32                       // combine blocks (x128 thr = NBOX)
#define NCELL  64                       // 8x8 spatial cells (100px), morton order

// Scratch (device globals: no allocation allowed in kernel_launch)
__device__ int    g_cnt[2 * NCELL];     // per-side per-cell counts (zeroed by combine)
__device__ float4 g_sP4[NBOX];          // spatially sorted preds
__device__ int    g_sPi[NBOX];          // original indices
__device__ float4 g_sT4[NBOX];          // spatially sorted targets
__device__ int    g_sTi[NBOX];
__device__ float4 g_pbb[32];            // pred-chunk bbox (mnx0, mxx2, mny0, mxy2) raw
__device__ float4 g_tbb[32];            // tgt-chunk bbox raw
__device__ unsigned long long g_best[NBOX]; // packed (ratio_bits<<32 | ~argOrig); 0 = none
__device__ float  g_rbS[NBLK];
__device__ int    g_rbC[NBLK];
__device__ double g_pG[CBLK];           // combine-block RepGT sln partials
__device__ int    g_pC[CBLK];           // combine-block RepGT counts
__device__ double g_pL[CBLK];           // combine-block smooth-L1 partials
__device__ unsigned int g_ticket;       // combine last-block ticket

__device__ __forceinline__ int cellOf(float x, float y) {
    int cx = (int)(x * 0.01f); cx = cx < 0 ? 0 : (cx > 7 ? 7 : cx);
    int cy = (int)(y * 0.01f); cy = cy < 0 ? 0 : (cy > 7 ? 7 : cy);
    return (cx & 1) | ((cy & 1) << 1) | ((cx & 2) << 1) |
           ((cy & 2) << 2) | ((cx & 4) << 2) | ((cy & 4) << 3);
}

// ---------------------------------------------------------------------------
// Kernel 0: fused rank + scatter + chunk bboxes. 8 blocks x 1024 as TWO
// 4-CTA clusters (cluster == side). Second cluster barrier orders the
// scatter writes before blocks 0/4 compute the per-128-chunk bboxes.
// ---------------------------------------------------------------------------
__global__ __launch_bounds__(1024) __cluster_dims__(4, 1, 1)
void sort_kernel(const float4* __restrict__ pred4,
                 const float4* __restrict__ tgt4)
{
    const int tid  = threadIdx.x;
    const int side = blockIdx.x >> 2;               // 0 = tgt, 1 = pred
    const int idx  = (blockIdx.x & 3) * 1024 + tid;
    const float4* src = side ? pred4 : tgt4;
    float4* dst  = side ? g_sP4 : g_sT4;
    int*    dsti = side ? g_sPi : g_sTi;
    const int lane = tid & 31, wrp = tid >> 5;

    if (blockIdx.x == 0 && tid == 0) g_ticket = 0u; // reset combine ticket

    __shared__ int sh[NCELL], sbase[NCELL], soff[NCELL];
    if (tid < NCELL) sh[tid] = 0;
    __syncthreads();

    const float4 v = src[idx];
    const int cell = cellOf(v.x, v.y);
    const int lr   = atomicAdd(&sh[cell], 1);
    __syncthreads();
    if (tid < NCELL) sbase[tid] = atomicAdd(&g_cnt[side * NCELL + tid], sh[tid]);
    __syncthreads();
    const int rank = sbase[cell] + lr;

    // ---- cluster barrier 1: all 4 blocks of this side have added counts ----
    __threadfence();
    asm volatile("barrier.cluster.arrive.aligned;" ::: "memory");
    asm volatile("barrier.cluster.wait.aligned;" ::: "memory");

    if (tid == 0) {
        int acc = 0;
        for (int c = 0; c < NCELL; ++c) { soff[c] = acc; acc += g_cnt[side * NCELL + c]; }
    }
    __syncthreads();

    const int pos = soff[cell] + rank;
    dst[pos]  = v;
    dsti[pos] = idx;

    // ---- cluster barrier 2: sorted arrays complete for this side ----
    __threadfence();
    asm volatile("barrier.cluster.arrive.aligned;" ::: "memory");
    asm volatile("barrier.cluster.wait.aligned;" ::: "memory");

    // chunk bboxes: block 0 -> tgt, block 4 -> pred (warp w owns chunk w)
    if ((blockIdx.x & 3) == 0) {
        const float4* d = side ? g_sP4 : g_sT4;
        float4* bb = side ? g_pbb : g_tbb;
        float mnx = 1e30f, mxx = -1e30f, mny = 1e30f, mxy = -1e30f;
        #pragma unroll
        for (int q = 0; q < 4; ++q) {
            const float4 bx4 = d[wrp * 128 + q * 32 + lane];
            mnx = fminf(mnx, bx4.x); mxx = fmaxf(mxx, bx4.z);
            mny = fminf(mny, bx4.y); mxy = fmaxf(mxy, bx4.w);
        }
        #pragma unroll
        for (int o = 16; o > 0; o >>= 1) {
            mnx = fminf(mnx, __shfl_xor_sync(0xffffffffu, mnx, o));
            mxx = fmaxf(mxx, __shfl_xor_sync(0xffffffffu, mxx, o));
            mny = fminf(mny, __shfl_xor_sync(0xffffffffu, mny, o));
            mxy = fmaxf(mxy, __shfl_xor_sync(0xffffffffu, mxy, o));
        }
        if (lane == 0) bb[wrp] = make_float4(mnx, mxx, mny, mxy);
    }
}

// ---------------------------------------------------------------------------
// Kernel 1: pair sweep. Pre-load block cull via precomputed chunk bboxes;
// survivors use g_pbb[bx] as the compaction bbox (no butterfly), then the
// R12 compaction + dense sweep.
// ---------------------------------------------------------------------------
__global__ __launch_bounds__(RPB)
void pair_kernel()
{
    const int tid = threadIdx.x;
    const int bx = blockIdx.x, by = blockIdx.y;
    const int b  = bx * 32 + by;
    const int lane = tid & 31, wrp = tid >> 5;

    // ---- block cull BEFORE any heavy loads (exact +1 convention) ----
    const float4 pb = g_pbb[bx];        // (mnx0, mxx2_raw, mny0, mxy2_raw)
    const float4 tb = g_tbb[by];
    const float pmnx = pb.x, pmxx = pb.y + 1.0f;
    const float pmny = pb.z, pmxy = pb.w + 1.0f;
    if (!((pmxx > tb.x) && (tb.y + 1.0f > pmnx) &&
          (pmxy > tb.z) && (tb.w + 1.0f > pmny))) {
        if (tid == 0) { g_rbS[b] = 0.0f; g_rbC[b] = 0; }
        return;                         // block-uniform
    }

    __shared__ float4 sT2[CHUNK];   // compacted targets {x0, y0, x2+1, y2+1}
    __shared__ float2 sAJ2[CHUNK];  // compacted (area+1conv, orig idx bits)
    __shared__ int sCnt[4], sBase[4], sN;

    // --- own pred row ---
    const int r = bx * RPB + tid;
    float4 p = g_sP4[r];
    const int iO = g_sPi[r];
    const float areaP = (p.z - p.x + 1.0f) * (p.w - p.y + 1.0f);
    p.z += 1.0f; p.w += 1.0f;

    // --- load my target, test vs pred-chunk bbox, deterministic compaction ---
    {
        float4 t = g_sT4[by * CHUNK + tid];
        const int jO = g_sTi[by * CHUNK + tid];
        const float a = (t.z - t.x + 1.0f) * (t.w - t.y + 1.0f);
        t.z += 1.0f; t.w += 1.0f;
        const bool pass = (pmxx > t.x) && (t.z > pmnx) &&
                          (pmxy > t.y) && (t.w > pmny);
        const unsigned m = __ballot_sync(0xffffffffu, pass);
        if (lane == 0) sCnt[wrp] = __popc(m);
        __syncthreads();
        if (tid == 0) {
            int acc = 0;
            #pragma unroll
            for (int w = 0; w < 4; ++w) { sBase[w] = acc; acc += sCnt[w]; }
            sN = acc;
        }
        __syncthreads();
        if (pass) {
            const int pos = sBase[wrp] + __popc(m & ((1u << lane) - 1u));
            sT2[pos]  = t;
            sAJ2[pos] = make_float2(a, __int_as_float(jO));
        }
    }
    __syncthreads();

    const int nAct = sN;
    float bI = 0.0f, bU = 1.0f;
    int   bA = 0;
    float rbS = 0.0f;
    int   rbC = 0;

    #pragma unroll 4
    for (int k = 0; k < nAct; ++k) {
        const float4 t  = sT2[k];
        const float2 aj = sAJ2[k];
        float iw = fminf(p.z, t.z) - fmaxf(p.x, t.x);
        float ih = fminf(p.w, t.w) - fmaxf(p.y, t.y);
        iw = fmaxf(iw, 0.0f);
        ih = fmaxf(ih, 0.0f);
        const float inter = iw * ih;
        const float ua    = areaP + aj.x - inter;
        const int   jO    = __float_as_int(aj.y);
        if ((jO != iO) && (inter * bU > bI * ua)) {
            bI = inter; bU = ua; bA = jO;
        }
        if ((jO < iO) && (inter > 0.0f)) {
            rbS += __fdividef(inter, ua);
            rbC += 1;
        }
    }

    if (bI > 0.0f) {
        const float ratio = bI / bU;
        const unsigned long long packed =
            ((unsigned long long)__float_as_uint(ratio) << 32) |
            (unsigned long long)(0xFFFFFFFFu - (unsigned)bA);
        atomicMax(&g_best[iO], packed);    // indexed by ORIGINAL row
    }

    #pragma unroll
    for (int o = 16; o > 0; o >>= 1) {
        rbS += __shfl_down_sync(0xffffffffu, rbS, o);
        rbC += __shfl_down_sync(0xffffffffu, rbC, o);
    }
    __shared__ float wS[RPB / 32];
    __shared__ int   wC[RPB / 32];
    if (lane == 0) { wS[wrp] = rbS; wC[wrp] = rbC; }
    __syncthreads();
    if (tid == 0) {
        float s = 0.0f; int c = 0;
        #pragma unroll
        for (int w = 0; w < RPB / 32; ++w) { s += wS[w]; c += wC[w]; }
        g_rbS[b] = s;
        g_rbC[b] = c;
    }
}

// ---------------------------------------------------------------------------
// Kernel 2: combine + (last block) reduce + broadcast (R12-identical).
// Zeroes g_cnt / g_best for the next graph replay.
// ---------------------------------------------------------------------------
__global__ __launch_bounds__(128)
void combine_kernel(const float4* __restrict__ pred4,
                    const float4* __restrict__ tgt4,
                    float* __restrict__ out)
{
    const int tid = threadIdx.x;
    const int r   = blockIdx.x * 128 + tid;
    const int lane = tid & 31, wrp = tid >> 5;

    if (blockIdx.x == 0 && tid < 2 * NCELL) g_cnt[tid] = 0;   // reset for next replay

    const float4 pe = pred4[r];
    const float4 te = tgt4[r];
    float slf = 0.0f;
    {
        float d;
        d = fabsf(pe.x - te.x); slf += (d < 1.0f) ? 0.5f * d * d : d - 0.5f;
        d = fabsf(pe.y - te.y); slf += (d < 1.0f) ? 0.5f * d * d : d - 0.5f;
        d = fabsf(pe.z - te.z); slf += (d < 1.0f) ? 0.5f * d * d : d - 0.5f;
        d = fabsf(pe.w - te.w); slf += (d < 1.0f) ? 0.5f * d * d : d - 0.5f;
    }

    const unsigned long long packed = g_best[r];
    g_best[r] = 0ull;                       // reset for next replay

    float sgf = 0.0f;
    int   cgi = 0;
    if (packed != 0ull) {
        const int bA = (int)(0xFFFFFFFFu - (unsigned)(packed & 0xFFFFFFFFull));
        const float4 g = tgt4[bA];
        const float iw = fmaxf(fminf(pe.z, g.z) - fmaxf(pe.x, g.x), 0.0f);
        const float ih = fmaxf(fminf(pe.w, g.w) - fmaxf(pe.y, g.y), 0.0f);
        const float garea = (g.z - g.x) * (g.w - g.y);
        const float iog = iw * ih / garea;
        if (iog > 0.9f) {
            sgf = (iog - 0.9f) / (1.0f - 0.9f) + 2.3025851f;
        } else {
            const float xc = fminf(fmaxf(iog, 0.0f), 1.0f - 1e-6f);
            sgf = -log1pf(-xc);
        }
        cgi = 1;
    }

    double sg = (double)sgf, sl = (double)slf;
    int cg = cgi;
    #pragma unroll
    for (int o = 16; o > 0; o >>= 1) {
        sg += __shfl_down_sync(0xffffffffu, sg, o);
        sl += __shfl_down_sync(0xffffffffu, sl, o);
        cg += __shfl_down_sync(0xffffffffu, cg, o);
    }
    __shared__ double wG[4], wL[4];
    __shared__ int    wCt[4];
    if (lane == 0) { wG[wrp] = sg; wL[wrp] = sl; wCt[wrp] = cg; }
    __syncthreads();

    __shared__ unsigned int sIsLast;
    if (tid == 0) {
        double tg = 0.0, tl = 0.0; int tc = 0;
        #pragma unroll
        for (int w = 0; w < 4; ++w) { tg += wG[w]; tl += wL[w]; tc += wCt[w]; }
        g_pG[blockIdx.x] = tg;
        g_pL[blockIdx.x] = tl;
        g_pC[blockIdx.x] = tc;
        __threadfence();
        sIsLast = (atomicAdd(&g_ticket, 1u) == CBLK - 1u) ? 1u : 0u;
    }
    __syncthreads();
    if (sIsLast == 0u) return;

    double tsg = 0.0, tsl = 0.0, trb = 0.0;
    int tcg = 0; long long tcb = 0;
    if (tid < CBLK) {
        tsg = __ldcg(&g_pG[tid]);
        tsl = __ldcg(&g_pL[tid]);
        tcg = __ldcg(&g_pC[tid]);
    }
    #pragma unroll
    for (int q = 0; q < NBLK / 128; ++q) {   // 8 rb partials per thread
        const int bb = q * 128 + tid;
        trb += (double)__ldcg(&g_rbS[bb]);
        tcb += (long long)__ldcg(&g_rbC[bb]);
    }

    #pragma unroll
    for (int o = 16; o > 0; o >>= 1) {
        tsg += __shfl_down_sync(0xffffffffu, tsg, o);
        tsl += __shfl_down_sync(0xffffffffu, tsl, o);
        trb += __shfl_down_sync(0xffffffffu, trb, o);
        tcg += __shfl_down_sync(0xffffffffu, tcg, o);
        tcb += __shfl_down_sync(0xffffffffu, tcb, o);
    }
    __shared__ double fG[4], fL[4], fR[4];
    __shared__ int    fC[4];
    __shared__ long long fB[4];
    __shared__ float sScalar;
    if (lane == 0) { fG[wrp] = tsg; fL[wrp] = tsl; fR[wrp] = trb;
                     fC[wrp] = tcg; fB[wrp] = tcb; }
    __syncthreads();
    if (tid == 0) {
        double ag = 0.0, al = 0.0, ar = 0.0;
        int ac = 0; long long ab = 0;
        #pragma unroll
        for (int w = 0; w < 4; ++w) {
            ag += fG[w]; al += fL[w]; ar += fR[w]; ac += fC[w]; ab += fB[w];
        }
        const float sl1    = (float)(al / (double)(NBOX * 4));
        const float repgt  = (ac > 0) ? (float)(ag / (double)ac) : 0.0f;
        const float repbox = (ab > 0) ? (float)(ar / (double)ab) : 0.0f;
        sScalar = sl1 + repgt + repbox;
    }
    __syncthreads();

    const float s = sScalar;
    float4* out4 = (float4*)out;
    const float4 v = make_float4(s, s, s, s);
    #pragma unroll
    for (int q = tid; q < NBOX / 4; q += 128) out4[q] = v;
}

// ---------------------------------------------------------------------------
extern "C" void kernel_launch(void* const* d_in, const int* in_sizes, int n_in,
                              void* d_out, int out_size)
{
    const float* pred = (const float*)d_in[0];
    const float* tgt  = (const float*)d_in[1];
    float* out = (float*)d_out;

    sort_kernel<<<8, 1024>>>((const float4*)pred, (const float4*)tgt);
    dim3 grid(32, 32);
    pair_kernel<<<grid, RPB>>>();
    combine_kernel<<<CBLK, 128>>>((const float4*)pred, (const float4*)tgt, out);
}

// round 16
// speedup vs baseline: 1.4649x; 1.4649x over previous
#include <cuda_runtime.h>
#include <math.h>

#define NBOX   4096
#define RPB    128                      // pred rows per pair block
#define CHUNK  128                      // targets per pair block
#define NBLK   1024                     // 32x32 pair blocks
#define CBLK   32                       // combine blocks (x128 thr = NBOX)
#define NCELL  64                       // 8x8 spatial cells (100px), morton order

// Scratch (device globals: no allocation allowed in kernel_launch)
__device__ int    g_cnt[NCELL];         // pred per-cell counts (zeroed by combine)
__device__ float4 g_sP4[NBOX];          // spatially sorted preds
__device__ int    g_sPi[NBOX];          // original indices
__device__ unsigned long long g_best[NBOX]; // packed (ratio_bits<<32 | ~argOrig); 0 = none
__device__ float  g_rbS[NBLK];
__device__ int    g_rbC[NBLK];
__device__ double g_pG[CBLK];           // combine-block RepGT sln partials
__device__ int    g_pC[CBLK];           // combine-block RepGT counts
__device__ double g_pL[CBLK];           // combine-block smooth-L1 partials
__device__ unsigned int g_ticket;       // combine last-block ticket

__device__ __forceinline__ int cellOf(float x, float y) {
    int cx = (int)(x * 0.01f); cx = cx < 0 ? 0 : (cx > 7 ? 7 : cx);
    int cy = (int)(y * 0.01f); cy = cy < 0 ? 0 : (cy > 7 ? 7 : cy);
    return (cx & 1) | ((cy & 1) << 1) | ((cx & 2) << 1) |
           ((cy & 2) << 2) | ((cx & 4) << 2) | ((cy & 4) << 3);
}

// ---------------------------------------------------------------------------
// Kernel 0: rank + scatter for PREDS ONLY. One 4-CTA cluster x 1024 threads.
// (Targets stay unsorted: pair culls targets individually, so their order is
// irrelevant; only pred spatial grouping matters for tight block bboxes.)
// Parallel smem prefix scan replaces the serial 64-global-load loop.
// ---------------------------------------------------------------------------
__global__ __launch_bounds__(1024) __cluster_dims__(4, 1, 1)
void sort_kernel(const float4* __restrict__ pred4)
{
    const int tid  = threadIdx.x;
    const int idx  = blockIdx.x * 1024 + tid;

    if (blockIdx.x == 0 && tid == 0) g_ticket = 0u; // reset combine ticket

    __shared__ int sh[NCELL], sbase[NCELL], sscan[NCELL], sfin[NCELL];
    if (tid < NCELL) sh[tid] = 0;
    __syncthreads();

    const float4 v = pred4[idx];
    const int cell = cellOf(v.x, v.y);
    const int lr   = atomicAdd(&sh[cell], 1);
    __syncthreads();
    if (tid < NCELL) sbase[tid] = atomicAdd(&g_cnt[tid], sh[tid]);
    __syncthreads();
    const int rank = sbase[cell] + lr;

    // ---- cluster barrier: all 4 blocks have added their counts ----
    __threadfence();
    asm volatile("barrier.cluster.arrive.aligned;" ::: "memory");
    asm volatile("barrier.cluster.wait.aligned;" ::: "memory");

    // cooperative load of final counts + Hillis-Steele inclusive scan in smem
    if (tid < NCELL) { sfin[tid] = g_cnt[tid]; sscan[tid] = sfin[tid]; }
    __syncthreads();
    #pragma unroll
    for (int o = 1; o < NCELL; o <<= 1) {
        int add = 0;
        if (tid < NCELL && tid >= o) add = sscan[tid - o];
        __syncthreads();
        if (tid < NCELL) sscan[tid] += add;
        __syncthreads();
    }

    const int pos = sscan[cell] - sfin[cell] + rank;   // exclusive + rank
    g_sP4[pos] = v;
    g_sPi[pos] = idx;
}

// ---------------------------------------------------------------------------
// Kernel 1: pair sweep with block-level target compaction (R12-identical
// except targets come straight from the UNSORTED input array).
// ---------------------------------------------------------------------------
__global__ __launch_bounds__(RPB)
void pair_kernel(const float4* __restrict__ tgt4)
{
    const int tid = threadIdx.x;
    const int bx = blockIdx.x, by = blockIdx.y;
    const int b  = bx * 32 + by;
    const int lane = tid & 31, wrp = tid >> 5;

    __shared__ float4 sT2[CHUNK];   // compacted targets {x0, y0, x2+1, y2+1}
    __shared__ float2 sAJ2[CHUNK];  // compacted (area+1conv, orig idx bits)
    __shared__ float4 sPB[4];       // per-warp pred bbox
    __shared__ int sCnt[4], sBase[4], sN;

    // --- own pred row + warp bbox ---
    const int r = bx * RPB + tid;
    float4 p = g_sP4[r];
    const int iO = g_sPi[r];
    const float areaP = (p.z - p.x + 1.0f) * (p.w - p.y + 1.0f);
    p.z += 1.0f; p.w += 1.0f;

    {
        float mnx = p.x, mxx = p.z, mny = p.y, mxy = p.w;
        #pragma unroll
        for (int o = 16; o > 0; o >>= 1) {
            mnx = fminf(mnx, __shfl_xor_sync(0xffffffffu, mnx, o));
            mxx = fmaxf(mxx, __shfl_xor_sync(0xffffffffu, mxx, o));
            mny = fminf(mny, __shfl_xor_sync(0xffffffffu, mny, o));
            mxy = fmaxf(mxy, __shfl_xor_sync(0xffffffffu, mxy, o));
        }
        if (lane == 0) sPB[wrp] = make_float4(mnx, mxx, mny, mxy);
    }
    __syncthreads();

    // block pred bbox (uniform)
    const float pmnx = fminf(fminf(sPB[0].x, sPB[1].x), fminf(sPB[2].x, sPB[3].x));
    const float pmxx = fmaxf(fmaxf(sPB[0].y, sPB[1].y), fmaxf(sPB[2].y, sPB[3].y));
    const float pmny = fminf(fminf(sPB[0].z, sPB[1].z), fminf(sPB[2].z, sPB[3].z));
    const float pmxy = fmaxf(fmaxf(sPB[0].w, sPB[1].w), fmaxf(sPB[2].w, sPB[3].w));

    // --- load my target (unsorted input), test vs block bbox, compaction ---
    {
        const int jO = by * CHUNK + tid;        // original index == position
        float4 t = tgt4[jO];
        const float a = (t.z - t.x + 1.0f) * (t.w - t.y + 1.0f);
        t.z += 1.0f; t.w += 1.0f;
        const bool pass = (pmxx > t.x) && (t.z > pmnx) &&
                          (pmxy > t.y) && (t.w > pmny);
        const unsigned m = __ballot_sync(0xffffffffu, pass);
        if (lane == 0) sCnt[wrp] = __popc(m);
        __syncthreads();
        if (tid == 0) {
            int acc = 0;
            #pragma unroll
            for (int w = 0; w < 4; ++w) { sBase[w] = acc; acc += sCnt[w]; }
            sN = acc;
        }
        __syncthreads();
        if (pass) {
            const int pos = sBase[wrp] + __popc(m & ((1u << lane) - 1u));
            sT2[pos]  = t;
            sAJ2[pos] = make_float2(a, __int_as_float(jO));
        }
    }
    __syncthreads();

    const int nAct = sN;
    if (nAct == 0) {
        if (tid == 0) { g_rbS[b] = 0.0f; g_rbC[b] = 0; }
        return;
    }

    float bI = 0.0f, bU = 1.0f;
    int   bA = 0;
    float rbS = 0.0f;
    int   rbC = 0;

    #pragma unroll 4
    for (int k = 0; k < nAct; ++k) {
        const float4 t  = sT2[k];
        const float2 aj = sAJ2[k];
        float iw = fminf(p.z, t.z) - fmaxf(p.x, t.x);
        float ih = fminf(p.w, t.w) - fmaxf(p.y, t.y);
        iw = fmaxf(iw, 0.0f);
        ih = fmaxf(ih, 0.0f);
        const float inter = iw * ih;
        const float ua    = areaP + aj.x - inter;
        const int   jO    = __float_as_int(aj.y);
        if ((jO != iO) && (inter * bU > bI * ua)) {
            bI = inter; bU = ua; bA = jO;
        }
        if ((jO < iO) && (inter > 0.0f)) {
            rbS += __fdividef(inter, ua);
            rbC += 1;
        }
    }

    if (bI > 0.0f) {
        const float ratio = bI / bU;
        const unsigned long long packed =
            ((unsigned long long)__float_as_uint(ratio) << 32) |
            (unsigned long long)(0xFFFFFFFFu - (unsigned)bA);
        atomicMax(&g_best[iO], packed);    // indexed by ORIGINAL row
    }

    #pragma unroll
    for (int o = 16; o > 0; o >>= 1) {
        rbS += __shfl_down_sync(0xffffffffu, rbS, o);
        rbC += __shfl_down_sync(0xffffffffu, rbC, o);
    }
    __shared__ float wS[RPB / 32];
    __shared__ int   wC[RPB / 32];
    if (lane == 0) { wS[wrp] = rbS; wC[wrp] = rbC; }
    __syncthreads();
    if (tid == 0) {
        float s = 0.0f; int c = 0;
        #pragma unroll
        for (int w = 0; w < RPB / 32; ++w) { s += wS[w]; c += wC[w]; }
        g_rbS[b] = s;
        g_rbC[b] = c;
    }
}

// ---------------------------------------------------------------------------
// Kernel 2: combine + (last block) reduce + broadcast (R12-identical).
// Zeroes g_cnt / g_best for the next graph replay.
// ---------------------------------------------------------------------------
__global__ __launch_bounds__(128)
void combine_kernel(const float4* __restrict__ pred4,
                    const float4* __restrict__ tgt4,
                    float* __restrict__ out)
{
    const int tid = threadIdx.x;
    const int r   = blockIdx.x * 128 + tid;
    const int lane = tid & 31, wrp = tid >> 5;

    if (blockIdx.x == 0 && tid < NCELL) g_cnt[tid] = 0;   // reset for next replay

    const float4 pe = pred4[r];
    const float4 te = tgt4[r];
    float slf = 0.0f;
    {
        float d;
        d = fabsf(pe.x - te.x); slf += (d < 1.0f) ? 0.5f * d * d : d - 0.5f;
        d = fabsf(pe.y - te.y); slf += (d < 1.0f) ? 0.5f * d * d : d - 0.5f;
        d = fabsf(pe.z - te.z); slf += (d < 1.0f) ? 0.5f * d * d : d - 0.5f;
        d = fabsf(pe.w - te.w); slf += (d < 1.0f) ? 0.5f * d * d : d - 0.5f;
    }

    const unsigned long long packed = g_best[r];
    g_best[r] = 0ull;                       // reset for next replay

    float sgf = 0.0f;
    int   cgi = 0;
    if (packed != 0ull) {
        const int bA = (int)(0xFFFFFFFFu - (unsigned)(packed & 0xFFFFFFFFull));
        const float4 g = tgt4[bA];
        const float iw = fmaxf(fminf(pe.z, g.z) - fmaxf(pe.x, g.x), 0.0f);
        const float ih = fmaxf(fminf(pe.w, g.w) - fmaxf(pe.y, g.y), 0.0f);
        const float garea = (g.z - g.x) * (g.w - g.y);
        const float iog = iw * ih / garea;
        if (iog > 0.9f) {
            sgf = (iog - 0.9f) / (1.0f - 0.9f) + 2.3025851f;
        } else {
            const float xc = fminf(fmaxf(iog, 0.0f), 1.0f - 1e-6f);
            sgf = -log1pf(-xc);
        }
        cgi = 1;
    }

    double sg = (double)sgf, sl = (double)slf;
    int cg = cgi;
    #pragma unroll
    for (int o = 16; o > 0; o >>= 1) {
        sg += __shfl_down_sync(0xffffffffu, sg, o);
        sl += __shfl_down_sync(0xffffffffu, sl, o);
        cg += __shfl_down_sync(0xffffffffu, cg, o);
    }
    __shared__ double wG[4], wL[4];
    __shared__ int    wCt[4];
    if (lane == 0) { wG[wrp] = sg; wL[wrp] = sl; wCt[wrp] = cg; }
    __syncthreads();

    __shared__ unsigned int sIsLast;
    if (tid == 0) {
        double tg = 0.0, tl = 0.0; int tc = 0;
        #pragma unroll
        for (int w = 0; w < 4; ++w) { tg += wG[w]; tl += wL[w]; tc += wCt[w]; }
        g_pG[blockIdx.x] = tg;
        g_pL[blockIdx.x] = tl;
        g_pC[blockIdx.x] = tc;
        __threadfence();
        sIsLast = (atomicAdd(&g_ticket, 1u) == CBLK - 1u) ? 1u : 0u;
    }
    __syncthreads();
    if (sIsLast == 0u) return;

    double tsg = 0.0, tsl = 0.0, trb = 0.0;
    int tcg = 0; long long tcb = 0;
    if (tid < CBLK) {
        tsg = __ldcg(&g_pG[tid]);
        tsl = __ldcg(&g_pL[tid]);
        tcg = __ldcg(&g_pC[tid]);
    }
    #pragma unroll
    for (int q = 0; q < NBLK / 128; ++q) {   // 8 rb partials per thread
        const int bb = q * 128 + tid;
        trb += (double)__ldcg(&g_rbS[bb]);
        tcb += (long long)__ldcg(&g_rbC[bb]);
    }

    #pragma unroll
    for (int o = 16; o > 0; o >>= 1) {
        tsg += __shfl_down_sync(0xffffffffu, tsg, o);
        tsl += __shfl_down_sync(0xffffffffu, tsl, o);
        trb += __shfl_down_sync(0xffffffffu, trb, o);
        tcg += __shfl_down_sync(0xffffffffu, tcg, o);
        tcb += __shfl_down_sync(0xffffffffu, tcb, o);
    }
    __shared__ double fG[4], fL[4], fR[4];
    __shared__ int    fC[4];
    __shared__ long long fB[4];
    __shared__ float sScalar;
    if (lane == 0) { fG[wrp] = tsg; fL[wrp] = tsl; fR[wrp] = trb;
                     fC[wrp] = tcg; fB[wrp] = tcb; }
    __syncthreads();
    if (tid == 0) {
        double ag = 0.0, al = 0.0, ar = 0.0;
        int ac = 0; long long ab = 0;
        #pragma unroll
        for (int w = 0; w < 4; ++w) {
            ag += fG[w]; al += fL[w]; ar += fR[w]; ac += fC[w]; ab += fB[w];
        }
        const float sl1    = (float)(al / (double)(NBOX * 4));
        const float repgt  = (ac > 0) ? (float)(ag / (double)ac) : 0.0f;
        const float repbox = (ab > 0) ? (float)(ar / (double)ab) : 0.0f;
        sScalar = sl1 + repgt + repbox;
    }
    __syncthreads();

    const float s = sScalar;
    float4* out4 = (float4*)out;
    const float4 v = make_float4(s, s, s, s);
    #pragma unroll
    for (int q = tid; q < NBOX / 4; q += 128) out4[q] = v;
}

// ---------------------------------------------------------------------------
extern "C" void kernel_launch(void* const* d_in, const int* in_sizes, int n_in,
                              void* d_out, int out_size)
{
    const float* pred = (const float*)d_in[0];
    const float* tgt  = (const float*)d_in[1];
    float* out = (float*)d_out;

    sort_kernel<<<4, 1024>>>((const float4*)pred);
    dim3 grid(32, 32);
    pair_kernel<<<grid, RPB>>>((const float4*)tgt);
    combine_kernel<<<CBLK, 128>>>((const float4*)pred, (const float4*)tgt, out);
}